// round 1
// baseline (speedup 1.0000x reference)
#include <cuda_runtime.h>

#define D       256
#define MMAX    8192
#define TOPK    32
#define INV_TAU 10.0f
#define PCOEF   0.25f      // BETA / (2*SIGMA^2) = 0.5/2
#define PTHRESH 30.0f      // exact-filter bound: need >=32 cands with p <= PTHRESH-20

#define QT 16              // queries per CTA tile
#define CT 128             // candidates per CTA tile
#define DT 64              // d-dim tile
#define KSTRIDE 68         // padded smem stride (floats), 272B rows stay 16B aligned

__device__ int   g_count;
__device__ int   g_ci[MMAX];
__device__ float g_cp[MMAX];
__device__ float g_qn[128 * D];
__device__ float g_logits[128 * MMAX];

__device__ __forceinline__ float neg_inf() { return __int_as_float(0xff800000); }

__global__ void reset_kernel() {
    if (threadIdx.x == 0) g_count = 0;
}

// Exact candidate filter: keep slots with penalty <= PTHRESH.
__global__ void filter_kernel(const float* __restrict__ times,
                              const float* __restrict__ qtime, int N) {
    int i = blockIdx.x * blockDim.x + threadIdx.x;
    if (i >= N) return;
    float dt = qtime[0] - times[i];
    float p  = PCOEF * dt * dt;
    if (p <= PTHRESH) {
        int pos = atomicAdd(&g_count, 1);
        if (pos < MMAX) { g_ci[pos] = i; g_cp[pos] = p; }
    }
}

// q = x / max(||x||, 1e-12), one block per query row (256 threads = D).
__global__ void qnorm_kernel(const float* __restrict__ q) {
    int b = blockIdx.x, t = threadIdx.x;
    float v = q[b * D + t];
    float s = v * v;
    #pragma unroll
    for (int o = 16; o > 0; o >>= 1) s += __shfl_xor_sync(0xffffffffu, s, o);
    __shared__ float ws[8];
    if ((t & 31) == 0) ws[t >> 5] = s;
    __syncthreads();
    if (t < 32) {
        float x = (t < 8) ? ws[t] : 0.0f;
        #pragma unroll
        for (int o = 4; o > 0; o >>= 1) x += __shfl_xor_sync(0xffffffffu, x, o);
        if (t == 0) ws[0] = x;
    }
    __syncthreads();
    float norm = fmaxf(sqrtf(ws[0]), 1e-12f);
    g_qn[b * D + t] = v / norm;
}

// logits[b][j] = (qn[b] . K[ci[j]]) / tau - p[j]   for j < count, else -inf.
// Tile: QT=16 queries x CT=128 candidates per CTA; 256 threads; each thread
// owns a 2x4 register block (rows {tq, tq+8}, cols {tc, tc+32, tc+64, tc+96}).
__global__ void logits_kernel(const float* __restrict__ Kbank) {
    __shared__ float qs[QT][DT];       // 4 KB
    __shared__ float ks[CT][KSTRIDE];  // ~34 KB, padded stride vs bank conflicts

    int count = min(g_count, MMAX);
    int cbase = blockIdx.x * CT;
    int qbase = blockIdx.y * QT;
    int t  = threadIdx.x;
    int tq = t >> 5;   // 0..7
    int tc = t & 31;   // 0..31

    float acc[2][4];
    #pragma unroll
    for (int i = 0; i < 2; i++)
        #pragma unroll
        for (int j = 0; j < 4; j++) acc[i][j] = 0.0f;

    int nvalid = min(max(count - cbase, 0), CT);
    if (nvalid > 0) {
        for (int db = 0; db < D; db += DT) {
            // stage q tile: 16x64 floats = 256 float4, one per thread
            {
                int row = t >> 4, col = (t & 15) * 4;
                *(float4*)&qs[row][col] =
                    *(const float4*)&g_qn[(qbase + row) * D + db + col];
            }
            // stage K tile: 128x64 floats = 2048 float4, 8 per thread
            #pragma unroll
            for (int i = 0; i < 8; i++) {
                int idx = t + i * 256;
                int row = idx >> 4, col = (idx & 15) * 4;
                if (row < nvalid) {
                    size_t n = (size_t)g_ci[cbase + row];
                    *(float4*)&ks[row][col] =
                        *(const float4*)&Kbank[n * D + db + col];
                }
            }
            __syncthreads();
            #pragma unroll
            for (int dd = 0; dd < DT; dd += 4) {
                float4 qa = *(const float4*)&qs[tq][dd];
                float4 qb = *(const float4*)&qs[tq + 8][dd];
                #pragma unroll
                for (int j = 0; j < 4; j++) {
                    float4 kv = *(const float4*)&ks[tc + j * 32][dd];
                    acc[0][j] = fmaf(qa.x, kv.x, acc[0][j]);
                    acc[0][j] = fmaf(qa.y, kv.y, acc[0][j]);
                    acc[0][j] = fmaf(qa.z, kv.z, acc[0][j]);
                    acc[0][j] = fmaf(qa.w, kv.w, acc[0][j]);
                    acc[1][j] = fmaf(qb.x, kv.x, acc[1][j]);
                    acc[1][j] = fmaf(qb.y, kv.y, acc[1][j]);
                    acc[1][j] = fmaf(qb.z, kv.z, acc[1][j]);
                    acc[1][j] = fmaf(qb.w, kv.w, acc[1][j]);
                }
            }
            __syncthreads();
        }
    }

    #pragma unroll
    for (int i = 0; i < 2; i++) {
        int qrow = qbase + tq + i * 8;
        #pragma unroll
        for (int j = 0; j < 4; j++) {
            int c = cbase + tc + j * 32;
            float val = (c < count) ? fmaf(acc[i][j], INV_TAU, -g_cp[c])
                                    : neg_inf();
            g_logits[qrow * MMAX + c] = val;
        }
    }
}

// Per-query exact top-32 (32 block-argmax passes over smem), softmax, V gather.
__global__ void topk_kernel(const float* __restrict__ Vbank,
                            float* __restrict__ out) {
    __shared__ float sl[MMAX];   // 32 KB
    __shared__ float rv[256];
    __shared__ int   rj[256];
    __shared__ float tv[TOPK];
    __shared__ int   tj[TOPK];
    __shared__ float attn[TOPK];

    int b = blockIdx.x, t = threadIdx.x;

    for (int j = t; j < MMAX; j += 256) sl[j] = g_logits[b * MMAX + j];
    __syncthreads();

    for (int k = 0; k < TOPK; k++) {
        float bv = neg_inf(); int bj = 0;
        #pragma unroll
        for (int j = t; j < MMAX; j += 256) {
            float v = sl[j];
            if (v > bv) { bv = v; bj = j; }
        }
        rv[t] = bv; rj[t] = bj;
        __syncthreads();
        #pragma unroll
        for (int s = 128; s > 0; s >>= 1) {
            if (t < s && rv[t + s] > rv[t]) { rv[t] = rv[t + s]; rj[t] = rj[t + s]; }
            __syncthreads();
        }
        if (t == 0) { tv[k] = rv[0]; tj[k] = rj[0]; sl[rj[0]] = neg_inf(); }
        __syncthreads();
    }

    // softmax over the 32 selected logits (tv[0] is the max)
    if (t < 32) {
        float e = expf(tv[t] - tv[0]);
        float s = e;
        #pragma unroll
        for (int o = 16; o > 0; o >>= 1) s += __shfl_xor_sync(0xffffffffu, s, o);
        attn[t] = e / s;
    }
    __syncthreads();

    // out[b][d] = sum_k attn[k] * V[ci[tj[k]]][d]   (d = t)
    float acc = 0.0f;
    #pragma unroll
    for (int k = 0; k < TOPK; k++) {
        size_t n = (size_t)g_ci[tj[k]];
        acc = fmaf(attn[k], Vbank[n * D + t], acc);
    }
    out[b * D + t] = acc;
}

extern "C" void kernel_launch(void* const* d_in, const int* in_sizes, int n_in,
                              void* d_out, int out_size) {
    const float* query = (const float*)d_in[0];
    const float* Kbank = (const float*)d_in[1];
    const float* Vbank = (const float*)d_in[2];
    const float* times = (const float*)d_in[3];
    const float* qtime = (const float*)d_in[4];
    float* out = (float*)d_out;

    int Bq = in_sizes[0] / D;   // 128
    int N  = in_sizes[3];       // 500000

    reset_kernel<<<1, 32>>>();
    filter_kernel<<<(N + 255) / 256, 256>>>(times, qtime, N);
    qnorm_kernel<<<Bq, 256>>>(query);
    dim3 gl(MMAX / CT, Bq / QT);
    logits_kernel<<<gl, 256>>>(Kbank);
    topk_kernel<<<Bq, 256>>>(Vbank, out);
}

// round 2
// speedup vs baseline: 1.6205x; 1.6205x over previous
#include <cuda_runtime.h>

#define D       256
#define MMAX    8192
#define TOPK    32
#define INV_TAU 10.0f
#define PCOEF   0.25f      // BETA / (2*SIGMA^2)
#define PTHRESH 30.0f      // exact-filter bound (>=32 cands with p <= PTHRESH-20 guaranteed)

#define QT 32              // queries per CTA tile
#define CT 128             // candidates per CTA tile
#define DT 64              // d-dim tile
#define KSTRIDE 68         // padded smem stride (floats); 16B-aligned rows, conflict-free LDS.128

__device__ int   g_count;
__device__ int   g_ci[MMAX];
__device__ float g_cp[MMAX];
__device__ float g_qn[128 * D];
__device__ float g_logits[128 * MMAX];

__device__ __forceinline__ float neg_inf() { return __int_as_float(0xff800000); }

__device__ __forceinline__ unsigned long long fma2(unsigned long long a,
                                                   unsigned long long b,
                                                   unsigned long long c) {
    unsigned long long d;
    asm("fma.rn.f32x2 %0, %1, %2, %3;" : "=l"(d) : "l"(a), "l"(b), "l"(c));
    return d;
}

// q-normalize (one block per query) + fold in the g_count reset (stream order
// guarantees this kernel completes before filter_kernel starts).
__global__ void qnorm_kernel(const float* __restrict__ q) {
    if (blockIdx.x == 0 && threadIdx.x == 0) g_count = 0;
    int b = blockIdx.x, t = threadIdx.x;
    float v = q[b * D + t];
    float s = v * v;
    #pragma unroll
    for (int o = 16; o > 0; o >>= 1) s += __shfl_xor_sync(0xffffffffu, s, o);
    __shared__ float ws[8];
    if ((t & 31) == 0) ws[t >> 5] = s;
    __syncthreads();
    if (t < 32) {
        float x = (t < 8) ? ws[t] : 0.0f;
        #pragma unroll
        for (int o = 4; o > 0; o >>= 1) x += __shfl_xor_sync(0xffffffffu, x, o);
        if (t == 0) ws[0] = x;
    }
    __syncthreads();
    float norm = fmaxf(sqrtf(ws[0]), 1e-12f);
    g_qn[b * D + t] = v / norm;
}

// Exact candidate filter: keep slots with penalty <= PTHRESH.
__global__ void filter_kernel(const float* __restrict__ times,
                              const float* __restrict__ qtime, int N) {
    int i = blockIdx.x * blockDim.x + threadIdx.x;
    if (i >= N) return;
    float dt = qtime[0] - times[i];
    float p  = PCOEF * dt * dt;
    if (p <= PTHRESH) {
        int pos = atomicAdd(&g_count, 1);
        if (pos < MMAX) { g_ci[pos] = i; g_cp[pos] = p; }
    }
}

// logits[b][j] = (qn[b] . K[ci[j]]) / tau - p[j]  for j < count, else -inf.
// QT=32 x CT=128 tile, 256 threads, 4x4 register block per thread; inner
// product uses packed f32x2 FMA (2 MACs/instr). q smem reads are warp
// broadcasts (all lanes in a warp share the same 4 q rows).
__global__ __launch_bounds__(256, 3) void logits_kernel(const float* __restrict__ Kbank) {
    __shared__ float qs[QT][DT];       // 8 KB
    __shared__ float ks[CT][KSTRIDE];  // ~34 KB
    __shared__ int   cis[CT];

    int count = min(g_count, MMAX);
    int cbase = blockIdx.x * CT;
    int qbase = blockIdx.y * QT;
    int t    = threadIdx.x;
    int w    = t >> 5;    // warp 0..7 -> q rows w*4 .. w*4+3
    int lane = t & 31;    // k cols lane, lane+32, lane+64, lane+96

    unsigned long long acc2[4][4];
    #pragma unroll
    for (int i = 0; i < 4; i++)
        #pragma unroll
        for (int j = 0; j < 4; j++) acc2[i][j] = 0ull;

    int nvalid = min(max(count - cbase, 0), CT);
    if (nvalid > 0) {
        if (t < CT) cis[t] = g_ci[cbase + t];
        __syncthreads();
        for (int db = 0; db < D; db += DT) {
            // stage q tile: 32x64 floats = 512 float4, 2 per thread
            #pragma unroll
            for (int i = 0; i < 2; i++) {
                int idx = t + i * 256;
                int row = idx >> 4, col = (idx & 15) * 4;
                *(float4*)&qs[row][col] =
                    *(const float4*)&g_qn[(qbase + row) * D + db + col];
            }
            // stage K tile: 128x64 floats = 2048 float4, 8 per thread
            #pragma unroll
            for (int i = 0; i < 8; i++) {
                int idx = t + i * 256;
                int row = idx >> 4, col = (idx & 15) * 4;
                if (row < nvalid) {
                    size_t n = (size_t)cis[row];
                    *(float4*)&ks[row][col] =
                        *(const float4*)&Kbank[n * D + db + col];
                }
            }
            __syncthreads();
            #pragma unroll
            for (int dd = 0; dd < DT; dd += 4) {
                ulonglong2 qv[4], kv[4];
                #pragma unroll
                for (int i = 0; i < 4; i++)
                    qv[i] = *(const ulonglong2*)&qs[w * 4 + i][dd];
                #pragma unroll
                for (int j = 0; j < 4; j++)
                    kv[j] = *(const ulonglong2*)&ks[lane + j * 32][dd];
                #pragma unroll
                for (int i = 0; i < 4; i++)
                    #pragma unroll
                    for (int j = 0; j < 4; j++) {
                        acc2[i][j] = fma2(qv[i].x, kv[j].x, acc2[i][j]);
                        acc2[i][j] = fma2(qv[i].y, kv[j].y, acc2[i][j]);
                    }
            }
            __syncthreads();
        }
    }

    #pragma unroll
    for (int i = 0; i < 4; i++) {
        int qrow = qbase + w * 4 + i;
        #pragma unroll
        for (int j = 0; j < 4; j++) {
            int c = cbase + lane + j * 32;
            float lo = __uint_as_float((unsigned)(acc2[i][j] & 0xffffffffull));
            float hi = __uint_as_float((unsigned)(acc2[i][j] >> 32));
            float dot = lo + hi;
            float val = (c < count) ? fmaf(dot, INV_TAU, -g_cp[c]) : neg_inf();
            g_logits[qrow * MMAX + c] = val;
        }
    }
}

// Exact top-32 via byte-wise radix select on order-preserving uint transform,
// then softmax (order-invariant) + V gather. One block per query.
__global__ __launch_bounds__(256) void topk_kernel(const float* __restrict__ Vbank,
                                                   float* __restrict__ out) {
    __shared__ unsigned su[MMAX];   // 32 KB transformed logits
    __shared__ int hist[256];
    __shared__ unsigned selu[TOPK];
    __shared__ int   selj[TOPK];
    __shared__ float attn[TOPK];
    __shared__ int s_b, s_above, s_cls, s_ngt, s_neq;

    int b = blockIdx.x, t = threadIdx.x;

    // load + monotone transform (float -> unsigned, order preserving)
    for (int j4 = t; j4 < MMAX / 4; j4 += 256) {
        float4 v = *(const float4*)&g_logits[b * MMAX + j4 * 4];
        unsigned b0 = __float_as_uint(v.x), b1 = __float_as_uint(v.y);
        unsigned b2 = __float_as_uint(v.z), b3 = __float_as_uint(v.w);
        su[j4 * 4 + 0] = (b0 & 0x80000000u) ? ~b0 : (b0 | 0x80000000u);
        su[j4 * 4 + 1] = (b1 & 0x80000000u) ? ~b1 : (b1 | 0x80000000u);
        su[j4 * 4 + 2] = (b2 & 0x80000000u) ? ~b2 : (b2 | 0x80000000u);
        su[j4 * 4 + 3] = (b3 & 0x80000000u) ? ~b3 : (b3 | 0x80000000u);
    }
    if (t == 0) { s_ngt = 0; s_neq = 0; }
    __syncthreads();

    unsigned prefix = 0, mask = 0;
    int need = TOPK;
    for (int shift = 24; shift >= 0; shift -= 8) {
        hist[t] = 0;
        __syncthreads();
        for (int j = t; j < MMAX; j += 256) {
            unsigned u = su[j];
            if ((u & mask) == prefix) atomicAdd(&hist[(u >> shift) & 255], 1);
        }
        __syncthreads();
        if (t < 32) {
            int lane = t;
            int lsum = 0;
            #pragma unroll
            for (int i = 0; i < 8; i++) lsum += hist[lane * 8 + i];
            int x = lsum;  // inclusive suffix sum over lanes (bins >= lane*8)
            #pragma unroll
            for (int o = 1; o < 32; o <<= 1) {
                int y = __shfl_down_sync(0xffffffffu, x, o);
                if (lane + o < 32) x += y;
            }
            unsigned ball = __ballot_sync(0xffffffffu, x >= need);
            int lstar = 31 - __clz(ball);
            int xnext = __shfl_sync(0xffffffffu, x, (lstar + 1) & 31);
            int above0 = (lstar == 31) ? 0 : xnext;
            if (lane == lstar) {
                int c = above0;
                int bb = lstar * 8 + 7;
                while (true) {
                    int h = hist[bb];
                    if (c + h >= need || bb == lstar * 8) break;
                    c += h; bb--;
                }
                s_b = bb; s_above = c; s_cls = hist[bb];
            }
        }
        __syncthreads();
        prefix |= ((unsigned)s_b) << shift;
        mask   |= 0xFFu << shift;
        need   -= s_above;
        if (s_cls == need) break;   // entire tie class is taken -> done
    }

    // collection: elements with truncated value > prefix are certain winners
    // (exactly TOPK-need of them); take `need` from the == class.
    int eqoff = TOPK - need;
    __syncthreads();
    for (int j = t; j < MMAX; j += 256) {
        unsigned u = su[j];
        unsigned m = u & mask;
        if (m > prefix) {
            int p = atomicAdd(&s_ngt, 1);
            selu[p] = u; selj[p] = j;
        } else if (m == prefix) {
            int p = atomicAdd(&s_neq, 1);
            if (p < need) { selu[eqoff + p] = u; selj[eqoff + p] = j; }
        }
    }
    __syncthreads();

    // softmax over the 32 selected logits (order-invariant)
    if (t < 32) {
        unsigned u = selu[t];
        unsigned bits = (u & 0x80000000u) ? (u ^ 0x80000000u) : ~u;
        float v = __int_as_float(bits);
        float m = v;
        #pragma unroll
        for (int o = 16; o > 0; o >>= 1) m = fmaxf(m, __shfl_xor_sync(0xffffffffu, m, o));
        float e = expf(v - m);
        float s = e;
        #pragma unroll
        for (int o = 16; o > 0; o >>= 1) s += __shfl_xor_sync(0xffffffffu, s, o);
        attn[t] = e / s;
        selj[t] = g_ci[selj[t]];   // candidate slot -> bank row
    }
    __syncthreads();

    float acc = 0.0f;
    #pragma unroll
    for (int k = 0; k < TOPK; k++) {
        acc = fmaf(attn[k], Vbank[(size_t)selj[k] * D + t], acc);
    }
    out[b * D + t] = acc;
}

extern "C" void kernel_launch(void* const* d_in, const int* in_sizes, int n_in,
                              void* d_out, int out_size) {
    const float* query = (const float*)d_in[0];
    const float* Kbank = (const float*)d_in[1];
    const float* Vbank = (const float*)d_in[2];
    const float* times = (const float*)d_in[3];
    const float* qtime = (const float*)d_in[4];
    float* out = (float*)d_out;

    int Bq = in_sizes[0] / D;   // 128
    int N  = in_sizes[3];       // 500000

    qnorm_kernel<<<Bq, 256>>>(query);                       // also resets g_count
    filter_kernel<<<(N + 255) / 256, 256>>>(times, qtime, N);
    dim3 gl(MMAX / CT, Bq / QT);
    logits_kernel<<<gl, 256>>>(Kbank);
    topk_kernel<<<Bq, 256>>>(Vbank, out);
}